// round 16
// baseline (speedup 1.0000x reference)
#include <cuda_runtime.h>
#include <cuda_fp16.h>
#include <math.h>
#include <stdint.h>

// ---------------- problem constants ----------------
#define B_SZ   2
#define SEQ    2048
#define DM     1024
#define DI     2048
#define DS     16
#define DTR    64
#define MROWS  (B_SZ * SEQ)      // 4096
#define E2     (2 * DI)          // 4096
#define XDBL_W 96
#define KSPL   8                 // split-K factor for K3
#define NCHK   8                 // scan chunks
#define CHKL   (SEQ / NCHK)      // 256 steps per chunk
#define NCHAN  (B_SZ * DI)       // 4096
#define NPAIR  (NCHAN / 2)       // 2048 channel pairs

// ---------------- scratch (device globals) ----------------
static __device__ float g_xz   [(size_t)MROWS * E2];     // K1 out fp32 (x_lin | z)
static __device__ float g_xdbl [(size_t)MROWS * XDBL_W];
static __device__ float g_delta[(size_t)MROWS * DI];
static __device__ float g_part [(size_t)KSPL * MROWS * XDBL_W];

// chunked-scan state: per (chunk, pair, sub): 4 floats
static __device__ float g_P   [(size_t)NCHK * NPAIR * 8 * 4];
static __device__ float g_hend[(size_t)NCHK * NPAIR * 8 * 4];

static __device__ __half g_hs [(size_t)MROWS * DM];
static __device__ __half g_w1 [(size_t)E2 * DM];
static __device__ __half g_xp [(size_t)128 * DI];      // x_proj padded 96->128 rows
static __device__ __half g_dw [(size_t)DI * DTR];
static __device__ __half g_ow [(size_t)DM * DI];
static __device__ __half g_xh [(size_t)MROWS * DI];    // conv output fp16
static __device__ __half g_xdh[(size_t)MROWS * XDBL_W];// x_dbl fp16
static __device__ __half g_yh [(size_t)MROWS * DI];    // scan output fp16

#define CIX(c, pair, sub) (((((size_t)(c)) * NPAIR + (pair)) * 8 + (sub)) * 4)

// ---------------- tensor-core helpers ----------------
__device__ __forceinline__ void ldsm_x4(uint32_t& r0, uint32_t& r1, uint32_t& r2, uint32_t& r3,
                                        const __half* p)
{
    uint32_t addr = (uint32_t)__cvta_generic_to_shared(p);
    asm volatile("ldmatrix.sync.aligned.m8n8.x4.shared.b16 {%0,%1,%2,%3}, [%4];\n"
                 : "=r"(r0), "=r"(r1), "=r"(r2), "=r"(r3) : "r"(addr));
}

__device__ __forceinline__ void mma_f16(float* c, const uint32_t* a, const uint32_t* b)
{
    asm volatile(
        "mma.sync.aligned.m16n8k16.row.col.f32.f16.f16.f32 "
        "{%0,%1,%2,%3}, {%4,%5,%6,%7}, {%8,%9}, {%0,%1,%2,%3};\n"
        : "+f"(c[0]), "+f"(c[1]), "+f"(c[2]), "+f"(c[3])
        : "r"(a[0]), "r"(a[1]), "r"(a[2]), "r"(a[3]), "r"(b[0]), "r"(b[1]));
}

__device__ __forceinline__ void cp16(void* dst, const void* src)
{
    uint32_t d = (uint32_t)__cvta_generic_to_shared(dst);
    asm volatile("cp.async.cg.shared.global [%0], [%1], 16;\n" :: "r"(d), "l"(src));
}
__device__ __forceinline__ void cp_commit() { asm volatile("cp.async.commit_group;\n"); }
template<int N>
__device__ __forceinline__ void cp_wait()   { asm volatile("cp.async.wait_group %0;\n" :: "n"(N)); }

// ---------------- fused fp32 -> fp16 conversion (single launch) ----------------
#define CN0 (MROWS * DM)
#define CN1 (E2 * DM)
#define CN2 (DM * DI)
#define CN3 (128 * DI)
#define CN4 (DI * DTR)
#define CTOT (CN0 + CN1 + CN2 + CN3 + CN4)

__device__ __forceinline__ void cvt4(const float* __restrict__ s, __half* __restrict__ d,
                                     int idx, int n_valid)
{
    float4 v = make_float4(0.f, 0.f, 0.f, 0.f);
    if (idx < n_valid) v = *reinterpret_cast<const float4*>(s + idx);
    __half h[4];
    h[0] = __float2half_rn(v.x);
    h[1] = __float2half_rn(v.y);
    h[2] = __float2half_rn(v.z);
    h[3] = __float2half_rn(v.w);
    *reinterpret_cast<uint2*>(d + idx) = *reinterpret_cast<uint2*>(h);
}

__global__ void cvt_all(const float* __restrict__ hs, const float* __restrict__ w1,
                        const float* __restrict__ ow, const float* __restrict__ xp,
                        const float* __restrict__ dw)
{
    int i4 = (blockIdx.x * blockDim.x + threadIdx.x) * 4;
    if (i4 < CN0)                       { cvt4(hs, g_hs, i4, CN0); return; }
    i4 -= CN0;
    if (i4 < CN1)                       { cvt4(w1, g_w1, i4, CN1); return; }
    i4 -= CN1;
    if (i4 < CN2)                       { cvt4(ow, g_ow, i4, CN2); return; }
    i4 -= CN2;
    if (i4 < CN3)                       { cvt4(xp, g_xp, i4, 96 * DI); return; }
    i4 -= CN3;
    if (i4 < CN4)                       { cvt4(dw, g_dw, i4, CN4); return; }
}

// ---------------- fp16 HMMA GEMM: 8 warps 32x64, BK=64, 2-stage double buffer ----------
// Block tile 128x128, 256 threads. Two __syncthreads per iter; prefetch distance 1
// (safe: end-of-compute barrier orders stage reads before its refill next iter).
#define BK     64
#define LDSMH  72                      // 64 + 8 pad halfs: conflict-free ldmatrix
#define TILEH  (128 * LDSMH)
#define STAGEH (2 * TILEH)             // A | B
#define NST    2
#define SMEM_BYTES (NST * STAGEH * (int)sizeof(__half))   // 73728

template<int EPI>
__global__ __launch_bounds__(256, 2)
void gemm_h(const __half* __restrict__ A, int lda,
            const __half* __restrict__ B, int ldb,
            float* __restrict__ C, int ldc,
            int M, int N, int K,
            int kzo, size_t czs,
            const float* __restrict__ bias)
{
    extern __shared__ __half smem[];

    const int tid  = threadIdx.x;
    const int lane = tid & 31;
    const int wid  = tid >> 5;
    const int wm   = wid & 3;          // 32-row slice
    const int wn   = wid >> 2;         // 64-col slice

    const int bm = blockIdx.y * 128;
    const int bn = blockIdx.x * 128;

    A += (size_t)blockIdx.z * kzo;
    B += (size_t)blockIdx.z * kzo;
    C += (size_t)blockIdx.z * czs;

    // loader: 2 threads/row, each 4x16B chunks
    const int lrow  = tid >> 1;          // 0..127
    const int lslot = (tid & 1) * 32;    // halfs

    float acc[2][8][4];
#pragma unroll
    for (int i = 0; i < 2; i++)
#pragma unroll
        for (int j = 0; j < 8; j++)
#pragma unroll
            for (int q = 0; q < 4; q++) acc[i][j][q] = 0.f;

    const int KT = K / BK;

    auto load_stage = [&](int s, int kt) {
        __half* sA = smem + s * STAGEH;
        __half* sB = sA + TILEH;
        int k0 = kt * BK;
        const __half* gA = A + (size_t)(bm + lrow) * lda + k0 + lslot;
        const __half* gB = B + (size_t)(bn + lrow) * ldb + k0 + lslot;
        __half* dA = sA + lrow * LDSMH + lslot;
        __half* dB = sB + lrow * LDSMH + lslot;
#pragma unroll
        for (int j = 0; j < 4; j++) {
            cp16(dA + j * 8, gA + j * 8);
            cp16(dB + j * 8, gB + j * 8);
        }
    };

    load_stage(0, 0);
    cp_commit();

    for (int it = 0; it < KT; it++) {
        if (it + 1 < KT) {
            load_stage((it + 1) & 1, it + 1);
            cp_commit();
            cp_wait<1>();
        } else {
            cp_wait<0>();
        }
        __syncthreads();

        const __half* sA = smem + (it & 1) * STAGEH;
        const __half* sB = sA + TILEH;

        uint32_t af[2][2][4], bf[2][8][2];

        auto ldf = [&](int q, int ks) {
            int arow_off = lane & 15;
            int akc = ks * 16 + (lane >> 4) * 8;
#pragma unroll
            for (int mt = 0; mt < 2; mt++) {
                int arow = wm * 32 + mt * 16 + arow_off;
                ldsm_x4(af[q][mt][0], af[q][mt][1], af[q][mt][2], af[q][mt][3],
                        sA + arow * LDSMH + akc);
            }
            int nrow_off = (lane & 7) + ((lane >> 4) & 1) * 8;
            int bkc = ks * 16 + ((lane >> 3) & 1) * 8;
#pragma unroll
            for (int ntp = 0; ntp < 4; ntp++) {
                int nrow = wn * 64 + ntp * 16 + nrow_off;
                ldsm_x4(bf[q][2 * ntp][0], bf[q][2 * ntp][1],
                        bf[q][2 * ntp + 1][0], bf[q][2 * ntp + 1][1],
                        sB + nrow * LDSMH + bkc);
            }
        };

        ldf(0, 0);
#pragma unroll
        for (int ks = 0; ks < 4; ks++) {
            if (ks < 3) ldf((ks + 1) & 1, ks + 1);   // prefetch next k16 fragments
#pragma unroll
            for (int mt = 0; mt < 2; mt++)
#pragma unroll
                for (int nt = 0; nt < 8; nt++)
                    mma_f16(acc[mt][nt], af[ks & 1][mt], bf[ks & 1][nt]);
        }
        __syncthreads();
    }

    // ---------- epilogue ----------
#pragma unroll
    for (int mt = 0; mt < 2; mt++) {
        int row = bm + wm * 32 + mt * 16 + (lane >> 2);
#pragma unroll
        for (int nt = 0; nt < 8; nt++) {
            int col = bn + wn * 64 + nt * 8 + (lane & 3) * 2;
            if (col >= N) continue;
#pragma unroll
            for (int half_ = 0; half_ < 2; half_++) {
                int r = row + half_ * 8;
                float v0 = acc[mt][nt][2 * half_ + 0];
                float v1 = acc[mt][nt][2 * half_ + 1];
                if (EPI == 1) {
                    v0 += bias[col];
                    v1 += bias[col + 1];
                    v0 = (v0 > 20.f) ? v0 : log1pf(expf(v0));
                    v1 = (v1 > 20.f) ? v1 : log1pf(expf(v1));
                }
                float2 st; st.x = v0; st.y = v1;
                *reinterpret_cast<float2*>(C + (size_t)r * ldc + col) = st;
            }
        }
    }
}

// ---------------- K3 split-K reduce ----------------
__global__ void k3_reduce_kernel()
{
    int i = blockIdx.x * blockDim.x + threadIdx.x;
    float s = 0.f;
#pragma unroll
    for (int z = 0; z < KSPL; z++)
        s += g_part[(size_t)z * MROWS * XDBL_W + i];
    g_xdbl[i] = s;
    g_xdh[i] = __float2half_rn(s);
}

// ---------------- depthwise conv + bias + silu; fp16 output ----------------
__global__ void conv_silu_kernel(const float* __restrict__ cw,
                                 const float* __restrict__ cb)
{
    int d = blockIdx.x * blockDim.x + threadIdx.x;
    int m = blockIdx.y;
    int l = m & (SEQ - 1);

    float acc = cb[d];
#pragma unroll
    for (int k = 0; k < 4; k++) {
        int ll = l - 3 + k;
        if (ll >= 0)
            acc = fmaf(cw[d * 4 + k], g_xz[(size_t)(m - 3 + k) * E2 + d], acc);
    }
    float s = acc / (1.f + expf(-acc));
    g_xh[(size_t)m * DI + d] = __float2half_rn(s);
}

// ---------------- chunked selective scan: 2 channels/thread ----------------
__global__ void scan_passA(const float* __restrict__ A_log)
{
    int t = blockIdx.x * blockDim.x + threadIdx.x;
    int chunk = t >> 14;
    int r = t & 16383;
    int sub  = r & 7;
    int pair = r >> 3;
    int chan0 = pair * 2;
    int b = chan0 >> 11;
    int d0 = chan0 & (DI - 1);

    float A00 = -expf(A_log[d0 * DS + sub * 2 + 0]);
    float A01 = -expf(A_log[d0 * DS + sub * 2 + 1]);
    float A10 = -expf(A_log[(d0 + 1) * DS + sub * 2 + 0]);
    float A11 = -expf(A_log[(d0 + 1) * DS + sub * 2 + 1]);

    float h00 = 0.f, h01 = 0.f, h10 = 0.f, h11 = 0.f;
    float P00 = 1.f, P01 = 1.f, P10 = 1.f, P11 = 1.f;

    size_t mb   = (size_t)b * SEQ + chunk * CHKL;
    size_t mrow = mb * DI + d0;
    size_t brow = mb * XDBL_W + DTR + sub * 2;

    float2  dt = *reinterpret_cast<const float2*>(g_delta + mrow);
    __half2 xh = *reinterpret_cast<const __half2*>(g_xh + mrow);
    float2  Bv = *reinterpret_cast<const float2*>(g_xdbl + brow);

    for (int l = 0; l < CHKL - 1; l++) {
        size_t mrow2 = mrow + DI;
        size_t brow2 = brow + XDBL_W;
        float2  dtn = *reinterpret_cast<const float2*>(g_delta + mrow2);
        __half2 xhn = *reinterpret_cast<const __half2*>(g_xh + mrow2);
        float2  Bn  = *reinterpret_cast<const float2*>(g_xdbl + brow2);

        float xv0 = __low2float(xh), xv1 = __high2float(xh);
        float dx0 = dt.x * xv0, dx1 = dt.y * xv1;
        float e00 = __expf(dt.x * A00), e01 = __expf(dt.x * A01);
        float e10 = __expf(dt.y * A10), e11 = __expf(dt.y * A11);
        P00 *= e00; P01 *= e01; P10 *= e10; P11 *= e11;
        h00 = fmaf(e00, h00, dx0 * Bv.x);
        h01 = fmaf(e01, h01, dx0 * Bv.y);
        h10 = fmaf(e10, h10, dx1 * Bv.x);
        h11 = fmaf(e11, h11, dx1 * Bv.y);

        dt = dtn; xh = xhn; Bv = Bn; mrow = mrow2; brow = brow2;
    }
    {
        float xv0 = __low2float(xh), xv1 = __high2float(xh);
        float dx0 = dt.x * xv0, dx1 = dt.y * xv1;
        float e00 = __expf(dt.x * A00), e01 = __expf(dt.x * A01);
        float e10 = __expf(dt.y * A10), e11 = __expf(dt.y * A11);
        P00 *= e00; P01 *= e01; P10 *= e10; P11 *= e11;
        h00 = fmaf(e00, h00, dx0 * Bv.x);
        h01 = fmaf(e01, h01, dx0 * Bv.y);
        h10 = fmaf(e10, h10, dx1 * Bv.x);
        h11 = fmaf(e11, h11, dx1 * Bv.y);
    }

    size_t o = CIX(chunk, pair, sub);
    float4 Pst; Pst.x = P00; Pst.y = P01; Pst.z = P10; Pst.w = P11;
    float4 Hst; Hst.x = h00; Hst.y = h01; Hst.z = h10; Hst.w = h11;
    *reinterpret_cast<float4*>(g_P + o)    = Pst;
    *reinterpret_cast<float4*>(g_hend + o) = Hst;
}

__global__ void scan_passB(const float* __restrict__ A_log,
                           const float* __restrict__ Dp)
{
    int t = blockIdx.x * blockDim.x + threadIdx.x;
    int chunk = t >> 14;
    int r = t & 16383;
    int sub  = r & 7;
    int pair = r >> 3;
    int chan0 = pair * 2;
    int b = chan0 >> 11;
    int d0 = chan0 & (DI - 1);

    float A00 = -expf(A_log[d0 * DS + sub * 2 + 0]);
    float A01 = -expf(A_log[d0 * DS + sub * 2 + 1]);
    float A10 = -expf(A_log[(d0 + 1) * DS + sub * 2 + 0]);
    float A11 = -expf(A_log[(d0 + 1) * DS + sub * 2 + 1]);
    float2 Dd = *reinterpret_cast<const float2*>(Dp + d0);

    float h00 = 0.f, h01 = 0.f, h10 = 0.f, h11 = 0.f;
    for (int c = 0; c < chunk; c++) {
        size_t p = CIX(c, pair, sub);
        float4 P  = *reinterpret_cast<const float4*>(g_P + p);
        float4 He = *reinterpret_cast<const float4*>(g_hend + p);
        h00 = fmaf(P.x, h00, He.x);
        h01 = fmaf(P.y, h01, He.y);
        h10 = fmaf(P.z, h10, He.z);
        h11 = fmaf(P.w, h11, He.w);
    }

    size_t mb   = (size_t)b * SEQ + chunk * CHKL;
    size_t mrow = mb * DI + d0;
    size_t zrow = mb * E2 + DI + d0;
    size_t brow = mb * XDBL_W + DTR + sub * 2;

    float2  dt = *reinterpret_cast<const float2*>(g_delta + mrow);
    __half2 xh = *reinterpret_cast<const __half2*>(g_xh + mrow);
    float2  zv = *reinterpret_cast<const float2*>(g_xz + zrow);
    float2  Bv = *reinterpret_cast<const float2*>(g_xdbl + brow);
    float2  Cv = *reinterpret_cast<const float2*>(g_xdbl + brow + DS);

    size_t yrow = mrow;
    for (int l = 0; l < CHKL; l++) {
        float2 dtn = make_float2(0.f, 0.f), zvn = dtn, Bn = dtn, Cn = dtn;
        __half2 xhn = __floats2half2_rn(0.f, 0.f);
        if (l + 1 < CHKL) {
            size_t mrow2 = mrow + DI;
            size_t brow2 = brow + XDBL_W;
            dtn = *reinterpret_cast<const float2*>(g_delta + mrow2);
            xhn = *reinterpret_cast<const __half2*>(g_xh + mrow2);
            zvn = *reinterpret_cast<const float2*>(g_xz + zrow + E2);
            Bn  = *reinterpret_cast<const float2*>(g_xdbl + brow2);
            Cn  = *reinterpret_cast<const float2*>(g_xdbl + brow2 + DS);
            mrow = mrow2; brow = brow2; zrow += E2;
        }

        float xv0 = __low2float(xh), xv1 = __high2float(xh);
        float dx0 = dt.x * xv0, dx1 = dt.y * xv1;
        float e00 = __expf(dt.x * A00), e01 = __expf(dt.x * A01);
        float e10 = __expf(dt.y * A10), e11 = __expf(dt.y * A11);
        h00 = fmaf(e00, h00, dx0 * Bv.x);
        h01 = fmaf(e01, h01, dx0 * Bv.y);
        h10 = fmaf(e10, h10, dx1 * Bv.x);
        h11 = fmaf(e11, h11, dx1 * Bv.y);

        float part0 = fmaf(h01, Cv.y, h00 * Cv.x);
        float part1 = fmaf(h11, Cv.y, h10 * Cv.x);
        part0 += __shfl_xor_sync(0xFFFFFFFFu, part0, 1);
        part1 += __shfl_xor_sync(0xFFFFFFFFu, part1, 1);
        part0 += __shfl_xor_sync(0xFFFFFFFFu, part0, 2);
        part1 += __shfl_xor_sync(0xFFFFFFFFu, part1, 2);
        part0 += __shfl_xor_sync(0xFFFFFFFFu, part0, 4);
        part1 += __shfl_xor_sync(0xFFFFFFFFu, part1, 4);

        if (sub == 0) {
            float sz0 = zv.x / (1.f + __expf(-zv.x));
            float sz1 = zv.y / (1.f + __expf(-zv.y));
            float y0 = (part0 + Dd.x * xv0) * sz0;
            float y1 = (part1 + Dd.y * xv1) * sz1;
            *reinterpret_cast<__half2*>(g_yh + yrow) = __floats2half2_rn(y0, y1);
            yrow += DI;
        }

        dt = dtn; xh = xhn; zv = zvn; Bv = Bn; Cv = Cn;
    }
}

// ---------------- launch ----------------
extern "C" void kernel_launch(void* const* d_in, const int* in_sizes, int n_in,
                              void* d_out, int out_size)
{
    const float* hs        = (const float*)d_in[0];
    const float* in_proj_w = (const float*)d_in[1];
    const float* conv_w    = (const float*)d_in[2];
    const float* conv_b    = (const float*)d_in[3];
    const float* x_proj_w  = (const float*)d_in[4];
    const float* dt_proj_w = (const float*)d_in[5];
    const float* dt_proj_b = (const float*)d_in[6];
    const float* A_log     = (const float*)d_in[7];
    const float* Dp        = (const float*)d_in[8];
    const float* out_w     = (const float*)d_in[9];
    float* out = (float*)d_out;

    float *p_xz, *p_part, *p_delta;
    cudaGetSymbolAddress((void**)&p_xz,    g_xz);
    cudaGetSymbolAddress((void**)&p_part,  g_part);
    cudaGetSymbolAddress((void**)&p_delta, g_delta);

    __half *p_hs, *p_w1, *p_xp, *p_dw, *p_ow, *p_xh, *p_xdh, *p_yh;
    cudaGetSymbolAddress((void**)&p_hs,  g_hs);
    cudaGetSymbolAddress((void**)&p_w1,  g_w1);
    cudaGetSymbolAddress((void**)&p_xp,  g_xp);
    cudaGetSymbolAddress((void**)&p_dw,  g_dw);
    cudaGetSymbolAddress((void**)&p_ow,  g_ow);
    cudaGetSymbolAddress((void**)&p_xh,  g_xh);
    cudaGetSymbolAddress((void**)&p_xdh, g_xdh);
    cudaGetSymbolAddress((void**)&p_yh,  g_yh);

    cudaFuncSetAttribute(gemm_h<0>, cudaFuncAttributeMaxDynamicSharedMemorySize, SMEM_BYTES);
    cudaFuncSetAttribute(gemm_h<1>, cudaFuncAttributeMaxDynamicSharedMemorySize, SMEM_BYTES);

    // C0: all conversions in one launch
    cvt_all<<<CTOT / 4 / 256, 256>>>(hs, in_proj_w, out_w, x_proj_w, dt_proj_w);

    // K1: xz = hs . in_proj_w^T   (4096 x 4096 x 1024) -> fp32
    gemm_h<0><<<dim3(E2 / 128, MROWS / 128, 1), 256, SMEM_BYTES>>>(
        p_hs, DM, p_w1, DM, p_xz, E2, MROWS, E2, DM, 0, 0, nullptr);

    // K2: depthwise conv + bias + silu
    conv_silu_kernel<<<dim3(DI / 256, MROWS), 256>>>(conv_w, conv_b);

    // K3: x_dbl partials = x . x_proj_w^T  (4096 x 96 x 2048), split-K x8 (K=256 each)
    gemm_h<0><<<dim3(1, MROWS / 128, KSPL), 256, SMEM_BYTES>>>(
        p_xh, DI, p_xp, DI, p_part, XDBL_W, MROWS, XDBL_W, DI / KSPL,
        DI / KSPL, (size_t)MROWS * XDBL_W, nullptr);
    k3_reduce_kernel<<<MROWS * XDBL_W / 256, 256>>>();

    // K4: delta = softplus(x_dbl[:, :64] . dt_proj_w^T + b)  (K=64 -> single iter)
    gemm_h<1><<<dim3(DI / 128, MROWS / 128, 1), 256, SMEM_BYTES>>>(
        p_xdh, XDBL_W, p_dw, DTR, p_delta, DI, MROWS, DI, DTR, 0, 0, dt_proj_b);

    // K5: chunked selective scan (passA -> passB with folded fixup)
    scan_passA<<<NCHK * 16384 / 256, 256>>>(A_log);
    scan_passB<<<NCHK * 16384 / 256, 256>>>(A_log, Dp);

    // K6: out = y . out_w^T       (4096 x 1024 x 2048) -> fp32
    gemm_h<0><<<dim3(DM / 128, MROWS / 128, 1), 256, SMEM_BYTES>>>(
        p_yh, DI, p_ow, DI, out, DM, MROWS, DM, DI, 0, 0, nullptr);
}

// round 17
// speedup vs baseline: 1.1991x; 1.1991x over previous
#include <cuda_runtime.h>
#include <cuda_fp16.h>
#include <math.h>
#include <stdint.h>

// ---------------- problem constants ----------------
#define B_SZ   2
#define SEQ    2048
#define DM     1024
#define DI     2048
#define DS     16
#define DTR    64
#define MROWS  (B_SZ * SEQ)      // 4096
#define E2     (2 * DI)          // 4096
#define XDBL_W 96
#define KSPL   8                 // split-K factor for K3
#define NCHK   8                 // scan chunks
#define CHKL   (SEQ / NCHK)      // 256 steps per chunk
#define NCHAN  (B_SZ * DI)       // 4096
#define NPAIR  (NCHAN / 2)       // 2048 channel pairs

// ---------------- scratch (device globals) ----------------
static __device__ float g_xz   [(size_t)MROWS * E2];     // K1 out fp32 (x_lin | z)
static __device__ float g_xdbl [(size_t)MROWS * XDBL_W];
static __device__ float g_delta[(size_t)MROWS * DI];
static __device__ float g_part [(size_t)KSPL * MROWS * XDBL_W];

// chunked-scan state: per (chunk, pair, sub): 4 floats
static __device__ float g_P   [(size_t)NCHK * NPAIR * 8 * 4];
static __device__ float g_hend[(size_t)NCHK * NPAIR * 8 * 4];

static __device__ __half g_hs [(size_t)MROWS * DM];
static __device__ __half g_w1 [(size_t)E2 * DM];
static __device__ __half g_xp [(size_t)128 * DI];      // x_proj padded 96->128 rows
static __device__ __half g_dw [(size_t)DI * DTR];
static __device__ __half g_ow [(size_t)DM * DI];
static __device__ __half g_xh [(size_t)MROWS * DI];    // conv output fp16
static __device__ __half g_xdh[(size_t)MROWS * XDBL_W];// x_dbl fp16
static __device__ __half g_yh [(size_t)MROWS * DI];    // scan output fp16

#define CIX(c, pair, sub) (((((size_t)(c)) * NPAIR + (pair)) * 8 + (sub)) * 4)

// ---------------- tensor-core helpers ----------------
__device__ __forceinline__ void ldsm_x4(uint32_t& r0, uint32_t& r1, uint32_t& r2, uint32_t& r3,
                                        const __half* p)
{
    uint32_t addr = (uint32_t)__cvta_generic_to_shared(p);
    asm volatile("ldmatrix.sync.aligned.m8n8.x4.shared.b16 {%0,%1,%2,%3}, [%4];\n"
                 : "=r"(r0), "=r"(r1), "=r"(r2), "=r"(r3) : "r"(addr));
}

__device__ __forceinline__ void mma_f16(float* c, const uint32_t* a, const uint32_t* b)
{
    asm volatile(
        "mma.sync.aligned.m16n8k16.row.col.f32.f16.f16.f32 "
        "{%0,%1,%2,%3}, {%4,%5,%6,%7}, {%8,%9}, {%0,%1,%2,%3};\n"
        : "+f"(c[0]), "+f"(c[1]), "+f"(c[2]), "+f"(c[3])
        : "r"(a[0]), "r"(a[1]), "r"(a[2]), "r"(a[3]), "r"(b[0]), "r"(b[1]));
}

__device__ __forceinline__ void cp16(void* dst, const void* src)
{
    uint32_t d = (uint32_t)__cvta_generic_to_shared(dst);
    asm volatile("cp.async.cg.shared.global [%0], [%1], 16;\n" :: "r"(d), "l"(src));
}
__device__ __forceinline__ void cp_commit() { asm volatile("cp.async.commit_group;\n"); }
template<int N>
__device__ __forceinline__ void cp_wait()   { asm volatile("cp.async.wait_group %0;\n" :: "n"(N)); }

// ---------------- fused fp32 -> fp16 conversion (single launch) ----------------
#define CN0 (MROWS * DM)
#define CN1 (E2 * DM)
#define CN2 (DM * DI)
#define CN3 (128 * DI)
#define CN4 (DI * DTR)
#define CTOT (CN0 + CN1 + CN2 + CN3 + CN4)

__device__ __forceinline__ void cvt4(const float* __restrict__ s, __half* __restrict__ d,
                                     int idx, int n_valid)
{
    float4 v = make_float4(0.f, 0.f, 0.f, 0.f);
    if (idx < n_valid) v = *reinterpret_cast<const float4*>(s + idx);
    __half h[4];
    h[0] = __float2half_rn(v.x);
    h[1] = __float2half_rn(v.y);
    h[2] = __float2half_rn(v.z);
    h[3] = __float2half_rn(v.w);
    *reinterpret_cast<uint2*>(d + idx) = *reinterpret_cast<uint2*>(h);
}

__global__ void cvt_all(const float* __restrict__ hs, const float* __restrict__ w1,
                        const float* __restrict__ ow, const float* __restrict__ xp,
                        const float* __restrict__ dw)
{
    int i4 = (blockIdx.x * blockDim.x + threadIdx.x) * 4;
    if (i4 < CN0)                       { cvt4(hs, g_hs, i4, CN0); return; }
    i4 -= CN0;
    if (i4 < CN1)                       { cvt4(w1, g_w1, i4, CN1); return; }
    i4 -= CN1;
    if (i4 < CN2)                       { cvt4(ow, g_ow, i4, CN2); return; }
    i4 -= CN2;
    if (i4 < CN3)                       { cvt4(xp, g_xp, i4, 96 * DI); return; }
    i4 -= CN3;
    if (i4 < CN4)                       { cvt4(dw, g_dw, i4, CN4); return; }
}

// ---------------- fp16 HMMA GEMM, 4-stage cp.async, single sync/iter, 2 CTAs/SM -------
// R12 config (verified local optimum): 8 warps, 32x64 warp tile, BK=32, NST=4, dist-2.
#define BK     32
#define LDSMH  40
#define TILEH  (128 * LDSMH)
#define STAGEH (2 * TILEH)
#define NST    4
#define SMEM_BYTES (NST * STAGEH * (int)sizeof(__half))   // 81920

template<int EPI>
__global__ __launch_bounds__(256, 2)
void gemm_h(const __half* __restrict__ A, int lda,
            const __half* __restrict__ B, int ldb,
            float* __restrict__ C, int ldc,
            int M, int N, int K,
            int kzo, size_t czs,
            const float* __restrict__ bias)
{
    extern __shared__ __half smem[];

    const int tid  = threadIdx.x;
    const int lane = tid & 31;
    const int wid  = tid >> 5;
    const int wm   = wid & 3;
    const int wn   = wid >> 2;

    const int bm = blockIdx.y * 128;
    const int bn = blockIdx.x * 128;

    A += (size_t)blockIdx.z * kzo;
    B += (size_t)blockIdx.z * kzo;
    C += (size_t)blockIdx.z * czs;

    const int lrow = tid >> 2;
    const int lslot = (tid & 3) * 8;

    float acc[2][8][4];
#pragma unroll
    for (int i = 0; i < 2; i++)
#pragma unroll
        for (int j = 0; j < 8; j++)
#pragma unroll
            for (int q = 0; q < 4; q++) acc[i][j][q] = 0.f;

    const int KT = K / BK;

    auto load_stage = [&](int s, int kt) {
        __half* sA = smem + s * STAGEH;
        __half* sB = sA + TILEH;
        int k0 = kt * BK;
#pragma unroll
        for (int p = 0; p < 2; p++) {
            int r = lrow + p * 64;
            cp16(sA + r * LDSMH + lslot, A + (size_t)(bm + r) * lda + k0 + lslot);
            cp16(sB + r * LDSMH + lslot, B + (size_t)(bn + r) * ldb + k0 + lslot);
        }
    };

    load_stage(0, 0);
    cp_commit();
    if (KT > 1) { load_stage(1, 1); cp_commit(); }

    for (int it = 0; it < KT; it++) {
        if (it + 2 < KT) {
            load_stage((it + 2) % NST, it + 2);
            cp_commit();
            cp_wait<2>();
        } else if (it + 1 < KT) {
            cp_wait<1>();
        } else {
            cp_wait<0>();
        }
        __syncthreads();          // single barrier per iter (NST=4, dist-2: WAR-safe)

        const __half* sA = smem + (it % NST) * STAGEH;
        const __half* sB = sA + TILEH;

        uint32_t af[2][2][4], bf[2][8][2];

        auto ldf = [&](int q, int ks) {
            int arow_off = lane & 15;
            int akc = ks * 16 + (lane >> 4) * 8;
#pragma unroll
            for (int mt = 0; mt < 2; mt++) {
                int arow = wm * 32 + mt * 16 + arow_off;
                ldsm_x4(af[q][mt][0], af[q][mt][1], af[q][mt][2], af[q][mt][3],
                        sA + arow * LDSMH + akc);
            }
            int nrow_off = (lane & 7) + ((lane >> 4) & 1) * 8;
            int bkc = ks * 16 + ((lane >> 3) & 1) * 8;
#pragma unroll
            for (int ntp = 0; ntp < 4; ntp++) {
                int nrow = wn * 64 + ntp * 16 + nrow_off;
                ldsm_x4(bf[q][2 * ntp][0], bf[q][2 * ntp][1],
                        bf[q][2 * ntp + 1][0], bf[q][2 * ntp + 1][1],
                        sB + nrow * LDSMH + bkc);
            }
        };

        ldf(0, 0);
#pragma unroll
        for (int ks = 0; ks < 2; ks++) {
            if (ks == 0) ldf(1, 1);
#pragma unroll
            for (int mt = 0; mt < 2; mt++)
#pragma unroll
                for (int nt = 0; nt < 8; nt++)
                    mma_f16(acc[mt][nt], af[ks][mt], bf[ks][nt]);
        }
    }

#pragma unroll
    for (int mt = 0; mt < 2; mt++) {
        int row = bm + wm * 32 + mt * 16 + (lane >> 2);
#pragma unroll
        for (int nt = 0; nt < 8; nt++) {
            int col = bn + wn * 64 + nt * 8 + (lane & 3) * 2;
            if (col >= N) continue;
#pragma unroll
            for (int half_ = 0; half_ < 2; half_++) {
                int r = row + half_ * 8;
                float v0 = acc[mt][nt][2 * half_ + 0];
                float v1 = acc[mt][nt][2 * half_ + 1];
                if (EPI == 1) {
                    v0 += bias[col];
                    v1 += bias[col + 1];
                    v0 = (v0 > 20.f) ? v0 : log1pf(expf(v0));
                    v1 = (v1 > 20.f) ? v1 : log1pf(expf(v1));
                }
                float2 st; st.x = v0; st.y = v1;
                *reinterpret_cast<float2*>(C + (size_t)r * ldc + col) = st;
            }
        }
    }
}

// ---------------- K3 split-K reduce ----------------
__global__ void k3_reduce_kernel()
{
    int i = blockIdx.x * blockDim.x + threadIdx.x;
    float s = 0.f;
#pragma unroll
    for (int z = 0; z < KSPL; z++)
        s += g_part[(size_t)z * MROWS * XDBL_W + i];
    g_xdbl[i] = s;
    g_xdh[i] = __float2half_rn(s);
}

// ---------------- depthwise conv + bias + silu; 8 m-positions per thread ---------------
// Thread handles one d, 8 consecutive m. Loads 11-row window (coalesced over d).
// FMA order per output identical to the original kernel -> bit-identical results.
#define CONV_MB 8
__global__ void conv_silu_kernel(const float* __restrict__ cw,
                                 const float* __restrict__ cb)
{
    int d  = blockIdx.x * blockDim.x + threadIdx.x;     // 0..DI-1
    int mb = blockIdx.y * CONV_MB;                      // window start
    int lb = mb & (SEQ - 1);                            // 0 only at sequence starts

    float w0 = cw[d * 4 + 0], w1 = cw[d * 4 + 1];
    float w2 = cw[d * 4 + 2], w3 = cw[d * 4 + 3];
    float bias = cb[d];

    float xwin[CONV_MB + 3];
#pragma unroll
    for (int j = 0; j < CONV_MB + 3; j++) {
        int m = mb - 3 + j;
        bool valid = (lb != 0) || (j >= 3);             // l<0 taps only when lb==0
        xwin[j] = valid ? g_xz[(size_t)m * E2 + d] : 0.f;
    }

#pragma unroll
    for (int j = 0; j < CONV_MB; j++) {
        float acc = bias;
        acc = fmaf(w0, xwin[j + 0], acc);
        acc = fmaf(w1, xwin[j + 1], acc);
        acc = fmaf(w2, xwin[j + 2], acc);
        acc = fmaf(w3, xwin[j + 3], acc);
        float s = acc / (1.f + expf(-acc));
        g_xh[(size_t)(mb + j) * DI + d] = __float2half_rn(s);
    }
}

// ---------------- chunked selective scan: 2 channels/thread ----------------
__global__ void scan_passA(const float* __restrict__ A_log)
{
    int t = blockIdx.x * blockDim.x + threadIdx.x;
    int chunk = t >> 14;
    int r = t & 16383;
    int sub  = r & 7;
    int pair = r >> 3;
    int chan0 = pair * 2;
    int b = chan0 >> 11;
    int d0 = chan0 & (DI - 1);

    float A00 = -expf(A_log[d0 * DS + sub * 2 + 0]);
    float A01 = -expf(A_log[d0 * DS + sub * 2 + 1]);
    float A10 = -expf(A_log[(d0 + 1) * DS + sub * 2 + 0]);
    float A11 = -expf(A_log[(d0 + 1) * DS + sub * 2 + 1]);

    float h00 = 0.f, h01 = 0.f, h10 = 0.f, h11 = 0.f;
    float P00 = 1.f, P01 = 1.f, P10 = 1.f, P11 = 1.f;

    size_t mb   = (size_t)b * SEQ + chunk * CHKL;
    size_t mrow = mb * DI + d0;
    size_t brow = mb * XDBL_W + DTR + sub * 2;

    float2  dt = *reinterpret_cast<const float2*>(g_delta + mrow);
    __half2 xh = *reinterpret_cast<const __half2*>(g_xh + mrow);
    float2  Bv = *reinterpret_cast<const float2*>(g_xdbl + brow);

    for (int l = 0; l < CHKL - 1; l++) {
        size_t mrow2 = mrow + DI;
        size_t brow2 = brow + XDBL_W;
        float2  dtn = *reinterpret_cast<const float2*>(g_delta + mrow2);
        __half2 xhn = *reinterpret_cast<const __half2*>(g_xh + mrow2);
        float2  Bn  = *reinterpret_cast<const float2*>(g_xdbl + brow2);

        float xv0 = __low2float(xh), xv1 = __high2float(xh);
        float dx0 = dt.x * xv0, dx1 = dt.y * xv1;
        float e00 = __expf(dt.x * A00), e01 = __expf(dt.x * A01);
        float e10 = __expf(dt.y * A10), e11 = __expf(dt.y * A11);
        P00 *= e00; P01 *= e01; P10 *= e10; P11 *= e11;
        h00 = fmaf(e00, h00, dx0 * Bv.x);
        h01 = fmaf(e01, h01, dx0 * Bv.y);
        h10 = fmaf(e10, h10, dx1 * Bv.x);
        h11 = fmaf(e11, h11, dx1 * Bv.y);

        dt = dtn; xh = xhn; Bv = Bn; mrow = mrow2; brow = brow2;
    }
    {
        float xv0 = __low2float(xh), xv1 = __high2float(xh);
        float dx0 = dt.x * xv0, dx1 = dt.y * xv1;
        float e00 = __expf(dt.x * A00), e01 = __expf(dt.x * A01);
        float e10 = __expf(dt.y * A10), e11 = __expf(dt.y * A11);
        P00 *= e00; P01 *= e01; P10 *= e10; P11 *= e11;
        h00 = fmaf(e00, h00, dx0 * Bv.x);
        h01 = fmaf(e01, h01, dx0 * Bv.y);
        h10 = fmaf(e10, h10, dx1 * Bv.x);
        h11 = fmaf(e11, h11, dx1 * Bv.y);
    }

    size_t o = CIX(chunk, pair, sub);
    float4 Pst; Pst.x = P00; Pst.y = P01; Pst.z = P10; Pst.w = P11;
    float4 Hst; Hst.x = h00; Hst.y = h01; Hst.z = h10; Hst.w = h11;
    *reinterpret_cast<float4*>(g_P + o)    = Pst;
    *reinterpret_cast<float4*>(g_hend + o) = Hst;
}

__global__ void scan_passB(const float* __restrict__ A_log,
                           const float* __restrict__ Dp)
{
    int t = blockIdx.x * blockDim.x + threadIdx.x;
    int chunk = t >> 14;
    int r = t & 16383;
    int sub  = r & 7;
    int pair = r >> 3;
    int chan0 = pair * 2;
    int b = chan0 >> 11;
    int d0 = chan0 & (DI - 1);

    float A00 = -expf(A_log[d0 * DS + sub * 2 + 0]);
    float A01 = -expf(A_log[d0 * DS + sub * 2 + 1]);
    float A10 = -expf(A_log[(d0 + 1) * DS + sub * 2 + 0]);
    float A11 = -expf(A_log[(d0 + 1) * DS + sub * 2 + 1]);
    float2 Dd = *reinterpret_cast<const float2*>(Dp + d0);

    float h00 = 0.f, h01 = 0.f, h10 = 0.f, h11 = 0.f;
    for (int c = 0; c < chunk; c++) {
        size_t p = CIX(c, pair, sub);
        float4 P  = *reinterpret_cast<const float4*>(g_P + p);
        float4 He = *reinterpret_cast<const float4*>(g_hend + p);
        h00 = fmaf(P.x, h00, He.x);
        h01 = fmaf(P.y, h01, He.y);
        h10 = fmaf(P.z, h10, He.z);
        h11 = fmaf(P.w, h11, He.w);
    }

    size_t mb   = (size_t)b * SEQ + chunk * CHKL;
    size_t mrow = mb * DI + d0;
    size_t zrow = mb * E2 + DI + d0;
    size_t brow = mb * XDBL_W + DTR + sub * 2;

    float2  dt = *reinterpret_cast<const float2*>(g_delta + mrow);
    __half2 xh = *reinterpret_cast<const __half2*>(g_xh + mrow);
    float2  zv = *reinterpret_cast<const float2*>(g_xz + zrow);
    float2  Bv = *reinterpret_cast<const float2*>(g_xdbl + brow);
    float2  Cv = *reinterpret_cast<const float2*>(g_xdbl + brow + DS);

    size_t yrow = mrow;
    for (int l = 0; l < CHKL; l++) {
        float2 dtn = make_float2(0.f, 0.f), zvn = dtn, Bn = dtn, Cn = dtn;
        __half2 xhn = __floats2half2_rn(0.f, 0.f);
        if (l + 1 < CHKL) {
            size_t mrow2 = mrow + DI;
            size_t brow2 = brow + XDBL_W;
            dtn = *reinterpret_cast<const float2*>(g_delta + mrow2);
            xhn = *reinterpret_cast<const __half2*>(g_xh + mrow2);
            zvn = *reinterpret_cast<const float2*>(g_xz + zrow + E2);
            Bn  = *reinterpret_cast<const float2*>(g_xdbl + brow2);
            Cn  = *reinterpret_cast<const float2*>(g_xdbl + brow2 + DS);
            mrow = mrow2; brow = brow2; zrow += E2;
        }

        float xv0 = __low2float(xh), xv1 = __high2float(xh);
        float dx0 = dt.x * xv0, dx1 = dt.y * xv1;
        float e00 = __expf(dt.x * A00), e01 = __expf(dt.x * A01);
        float e10 = __expf(dt.y * A10), e11 = __expf(dt.y * A11);
        h00 = fmaf(e00, h00, dx0 * Bv.x);
        h01 = fmaf(e01, h01, dx0 * Bv.y);
        h10 = fmaf(e10, h10, dx1 * Bv.x);
        h11 = fmaf(e11, h11, dx1 * Bv.y);

        float part0 = fmaf(h01, Cv.y, h00 * Cv.x);
        float part1 = fmaf(h11, Cv.y, h10 * Cv.x);
        part0 += __shfl_xor_sync(0xFFFFFFFFu, part0, 1);
        part1 += __shfl_xor_sync(0xFFFFFFFFu, part1, 1);
        part0 += __shfl_xor_sync(0xFFFFFFFFu, part0, 2);
        part1 += __shfl_xor_sync(0xFFFFFFFFu, part1, 2);
        part0 += __shfl_xor_sync(0xFFFFFFFFu, part0, 4);
        part1 += __shfl_xor_sync(0xFFFFFFFFu, part1, 4);

        if (sub == 0) {
            float sz0 = zv.x / (1.f + __expf(-zv.x));
            float sz1 = zv.y / (1.f + __expf(-zv.y));
            float y0 = (part0 + Dd.x * xv0) * sz0;
            float y1 = (part1 + Dd.y * xv1) * sz1;
            *reinterpret_cast<__half2*>(g_yh + yrow) = __floats2half2_rn(y0, y1);
            yrow += DI;
        }

        dt = dtn; xh = xhn; zv = zvn; Bv = Bn; Cv = Cn;
    }
}

// ---------------- launch ----------------
extern "C" void kernel_launch(void* const* d_in, const int* in_sizes, int n_in,
                              void* d_out, int out_size)
{
    const float* hs        = (const float*)d_in[0];
    const float* in_proj_w = (const float*)d_in[1];
    const float* conv_w    = (const float*)d_in[2];
    const float* conv_b    = (const float*)d_in[3];
    const float* x_proj_w  = (const float*)d_in[4];
    const float* dt_proj_w = (const float*)d_in[5];
    const float* dt_proj_b = (const float*)d_in[6];
    const float* A_log     = (const float*)d_in[7];
    const float* Dp        = (const float*)d_in[8];
    const float* out_w     = (const float*)d_in[9];
    float* out = (float*)d_out;

    float *p_xz, *p_part, *p_delta;
    cudaGetSymbolAddress((void**)&p_xz,    g_xz);
    cudaGetSymbolAddress((void**)&p_part,  g_part);
    cudaGetSymbolAddress((void**)&p_delta, g_delta);

    __half *p_hs, *p_w1, *p_xp, *p_dw, *p_ow, *p_xh, *p_xdh, *p_yh;
    cudaGetSymbolAddress((void**)&p_hs,  g_hs);
    cudaGetSymbolAddress((void**)&p_w1,  g_w1);
    cudaGetSymbolAddress((void**)&p_xp,  g_xp);
    cudaGetSymbolAddress((void**)&p_dw,  g_dw);
    cudaGetSymbolAddress((void**)&p_ow,  g_ow);
    cudaGetSymbolAddress((void**)&p_xh,  g_xh);
    cudaGetSymbolAddress((void**)&p_xdh, g_xdh);
    cudaGetSymbolAddress((void**)&p_yh,  g_yh);

    cudaFuncSetAttribute(gemm_h<0>, cudaFuncAttributeMaxDynamicSharedMemorySize, SMEM_BYTES);
    cudaFuncSetAttribute(gemm_h<1>, cudaFuncAttributeMaxDynamicSharedMemorySize, SMEM_BYTES);

    // C0: all conversions in one launch
    cvt_all<<<CTOT / 4 / 256, 256>>>(hs, in_proj_w, out_w, x_proj_w, dt_proj_w);

    // K1: xz = hs . in_proj_w^T   (4096 x 4096 x 1024) -> fp32
    gemm_h<0><<<dim3(E2 / 128, MROWS / 128, 1), 256, SMEM_BYTES>>>(
        p_hs, DM, p_w1, DM, p_xz, E2, MROWS, E2, DM, 0, 0, nullptr);

    // K2: depthwise conv + bias + silu (8 m-rows per thread)
    conv_silu_kernel<<<dim3(DI / 256, MROWS / CONV_MB), 256>>>(conv_w, conv_b);

    // K3: x_dbl partials = x . x_proj_w^T  (4096 x 96 x 2048), split-K x8
    gemm_h<0><<<dim3(1, MROWS / 128, KSPL), 256, SMEM_BYTES>>>(
        p_xh, DI, p_xp, DI, p_part, XDBL_W, MROWS, XDBL_W, DI / KSPL,
        DI / KSPL, (size_t)MROWS * XDBL_W, nullptr);
    k3_reduce_kernel<<<MROWS * XDBL_W / 256, 256>>>();

    // K4: delta = softplus(x_dbl[:, :64] . dt_proj_w^T + b) -> fp32
    gemm_h<1><<<dim3(DI / 128, MROWS / 128, 1), 256, SMEM_BYTES>>>(
        p_xdh, XDBL_W, p_dw, DTR, p_delta, DI, MROWS, DI, DTR, 0, 0, dt_proj_b);

    // K5: chunked selective scan (passA -> passB with folded fixup)
    scan_passA<<<NCHK * 16384 / 256, 256>>>(A_log);
    scan_passB<<<NCHK * 16384 / 256, 256>>>(A_log, Dp);

    // K6: out = y . out_w^T       (4096 x 1024 x 2048) -> fp32
    gemm_h<0><<<dim3(DM / 128, MROWS / 128, 1), 256, SMEM_BYTES>>>(
        p_yh, DI, p_ow, DI, out, DM, MROWS, DM, DI, 0, 0, nullptr);
}